// round 8
// baseline (speedup 1.0000x reference)
#include <cuda_runtime.h>
#include <cuda_fp16.h>
#include <math.h>

#define NN 50000
#define NE 800000
#define IND 128
#define OUTD 64
#define THALF 64
#define TABN 4096

// sqrt(1/128)
#define TSCALE 0.08838834764831845f

// ---------------- scratch (static __device__, no allocations) ----------------
__device__ float  g_p1[IND];
__device__ float  g_p2[IND];
__device__ float  g_q[2 * THALF];
__device__ float  g_tab[TABN + 1];
__device__ float  g_WvT[IND * OUTD];          // [k][c] layout
__device__ float  g_s1[NN];
__device__ float  g_s2[NN];
__device__ __half g_hv[NN * OUTD];            // fp16 value rows (halves gather BW)
__device__ float2 g_pair[NE];                 // (w=exp(leaky(e)), bitcast(src))
__device__ int    g_cnt[NN];                  // zero-init at load; self-restoring
__device__ int    g_off[NN + 1];
__device__ int    g_cur[NN];

// ---------------- packed f32x2 helpers ---------------------------------------
__device__ __forceinline__ unsigned long long fma2(unsigned long long a,
                                                   unsigned long long b,
                                                   unsigned long long c) {
    unsigned long long d;
    asm("fma.rn.f32x2 %0, %1, %2, %3;" : "=l"(d) : "l"(a), "l"(b), "l"(c));
    return d;
}
__device__ __forceinline__ unsigned long long splat2(float x) {
    unsigned long long d;
    asm("mov.b64 %0, {%1, %1};" : "=l"(d) : "f"(x));
    return d;
}
__device__ __forceinline__ float2 unpack2(unsigned long long v) {
    float lo, hi;
    asm("mov.b64 {%0, %1}, %2;" : "=f"(lo), "=f"(hi) : "l"(v));
    return make_float2(lo, hi);
}

// ---------------- fused setup kernel (weights-only prep) ---------------------
__global__ void k_setup(const float* __restrict__ W, const float* __restrict__ Wt,
                        const float* __restrict__ a, const float* __restrict__ Wv,
                        const float* __restrict__ omega) {
    int b = blockIdx.x;
    int t = threadIdx.x;

    if (b == 0) {
        if (t < 128) {
            float s = 0.f;
            #pragma unroll 8
            for (int i = 0; i < 64; i++) s += W[i * 128 + t] * a[i];
            g_p1[t] = s;
        } else {
            int k = t - 128;
            float s = 0.f;
            #pragma unroll 8
            for (int i = 0; i < 64; i++) s += W[i * 128 + k] * a[64 + i];
            g_p2[k] = s;
        }
    } else if (b == 1) {
        if (t < 128) {
            float s = 0.f;
            #pragma unroll 8
            for (int i = 0; i < 64; i++) s += Wt[i * 128 + t] * a[128 + i];
            g_q[t] = s;
        }
    } else if (b < 19) {
        __shared__ float qs[128];
        if (t < 128) {
            float s = 0.f;
            #pragma unroll 8
            for (int i = 0; i < 64; i++) s += Wt[i * 128 + t] * a[128 + i];
            qs[t] = s;
        }
        __syncthreads();
        int idx = (b - 2) * 256 + t;
        if (idx <= TABN) {
            float tt = (float)idx / (float)TABN;
            float s = 0.f;
            #pragma unroll 4
            for (int j = 0; j < THALF; j++) {
                float sn, cs;
                __sincosf(tt * omega[j], &sn, &cs);
                s += sn * qs[2 * j] + cs * qs[2 * j + 1];
            }
            g_tab[idx] = s * TSCALE;
        }
    } else {
        int j = (b - 19) * 256 + t;        // 0..8191
        int c = j & 63;
        int k = j >> 6;
        g_WvT[j] = Wv[c * 128 + k];
    }
}

// ---------------- per-node attention scalars s1/s2 (warp per node) -----------
__global__ void k_s12(const float* __restrict__ x) {
    int n = blockIdx.x * 8 + (threadIdx.x >> 5);
    int lane = threadIdx.x & 31;
    if (n >= NN) return;
    float4 v  = ((const float4*)(x + (size_t)n * IND))[lane];
    float4 p1 = ((const float4*)g_p1)[lane];
    float4 p2 = ((const float4*)g_p2)[lane];
    float d1 = v.x * p1.x + v.y * p1.y + v.z * p1.z + v.w * p1.w;
    float d2 = v.x * p2.x + v.y * p2.y + v.z * p2.z + v.w * p2.w;
    #pragma unroll
    for (int o = 16; o; o >>= 1) {
        d1 += __shfl_xor_sync(0xffffffffu, d1, o);
        d2 += __shfl_xor_sync(0xffffffffu, d2, o);
    }
    if (lane == 0) { g_s1[n] = d1; g_s2[n] = d2; }
}

// ---------------- hv = X @ Wv^T (packed f32x2 GEMM, fp16 output) -------------
__global__ void __launch_bounds__(128) k_hv(const float* __restrict__ x) {
    __shared__ float sX[64][68];   // row stride 68 floats (16B aligned, no conflicts)
    __shared__ float sB[64][64];

    int n0 = blockIdx.x * 64;
    int tid = threadIdx.x;
    int tr = (tid >> 3) * 4;
    int tc = (tid & 7) * 8;

    unsigned long long acc[4][4];  // [row][col-pair], 2 fp32 per entry
    #pragma unroll
    for (int r = 0; r < 4; r++)
        #pragma unroll
        for (int c = 0; c < 4; c++) acc[r][c] = 0ull;

    #pragma unroll
    for (int kt = 0; kt < 2; kt++) {
        for (int i = tid; i < 1024; i += 128) {
            int r  = i >> 4;
            int c4 = i & 15;
            int n = n0 + r;
            float4 v = (n < NN)
                ? *(const float4*)(x + (size_t)n * 128 + kt * 64 + c4 * 4)
                : make_float4(0.f, 0.f, 0.f, 0.f);
            *(float4*)&sX[r][c4 * 4] = v;
        }
        for (int i = tid; i < 1024; i += 128) {
            ((float4*)&sB[0][0])[i] = ((const float4*)(g_WvT + kt * 64 * 64))[i];
        }
        __syncthreads();

        #pragma unroll 4
        for (int kk = 0; kk < 64; kk += 4) {
            float4 xr[4];
            #pragma unroll
            for (int r = 0; r < 4; r++) xr[r] = *(float4*)&sX[tr + r][kk];
            #pragma unroll
            for (int u = 0; u < 4; u++) {
                ulonglong2 bp0 = *(ulonglong2*)&sB[kk + u][tc];
                ulonglong2 bp1 = *(ulonglong2*)&sB[kk + u][tc + 4];
                #pragma unroll
                for (int r = 0; r < 4; r++) {
                    float xv = (u == 0) ? xr[r].x : (u == 1) ? xr[r].y
                             : (u == 2) ? xr[r].z : xr[r].w;
                    unsigned long long xs = splat2(xv);
                    acc[r][0] = fma2(xs, bp0.x, acc[r][0]);
                    acc[r][1] = fma2(xs, bp0.y, acc[r][1]);
                    acc[r][2] = fma2(xs, bp1.x, acc[r][2]);
                    acc[r][3] = fma2(xs, bp1.y, acc[r][3]);
                }
            }
        }
        __syncthreads();
    }

    #pragma unroll
    for (int r = 0; r < 4; r++) {
        int n = n0 + tr + r;
        if (n < NN) {
            __half2 h[4];
            #pragma unroll
            for (int c = 0; c < 4; c++) {
                float2 f = unpack2(acc[r][c]);
                h[c] = __floats2half2_rn(f.x, f.y);
            }
            *(uint4*)(g_hv + (size_t)n * 64 + tc) =
                make_uint4(*(unsigned*)&h[0], *(unsigned*)&h[1],
                           *(unsigned*)&h[2], *(unsigned*)&h[3]);
        }
    }
}

// ---------------- degree histogram (8 edges per thread, 2x int4 load) --------
__global__ void k_count(const int* __restrict__ dst) {
    int i = blockIdx.x * 256 + threadIdx.x;      // NE/8 = 100000 threads
    if (i * 8 >= NE) return;
    int4 a4 = ((const int4*)dst)[i * 2];
    int4 b4 = ((const int4*)dst)[i * 2 + 1];
    atomicAdd(&g_cnt[a4.x], 1);
    atomicAdd(&g_cnt[a4.y], 1);
    atomicAdd(&g_cnt[a4.z], 1);
    atomicAdd(&g_cnt[a4.w], 1);
    atomicAdd(&g_cnt[b4.x], 1);
    atomicAdd(&g_cnt[b4.y], 1);
    atomicAdd(&g_cnt[b4.z], 1);
    atomicAdd(&g_cnt[b4.w], 1);
}

// ---------------- single-kernel scan: g_cnt -> g_off/g_cur, self-zeroing -----
// One block, 1024 threads, 52 contiguous elements per thread (int4-aligned).
// Stage 1: independent int4 chunk sums (high MLP). Block scan via shuffles.
// Stage 2: register-carried writeback of prefixes; zero g_cnt for next replay.
__global__ void __launch_bounds__(1024) k_scanall() {
    const int C = 52;   // 1024*52 = 53248 >= NN; NN%4==0 so int4 bounds are safe
    __shared__ int warpsum[32];
    int tid = threadIdx.x;
    int lane = tid & 31;
    int wid  = tid >> 5;
    int base = tid * C;

    int s = 0;
    #pragma unroll
    for (int j = 0; j < C; j += 4) {
        int idx = base + j;
        if (idx < NN) {
            int4 v = *(const int4*)&g_cnt[idx];
            s += (v.x + v.y) + (v.z + v.w);
        }
    }

    // block-wide exclusive scan of per-thread sums
    int x = s;
    #pragma unroll
    for (int o = 1; o < 32; o <<= 1) {
        int y = __shfl_up_sync(0xffffffffu, x, o);
        if (lane >= o) x += y;
    }
    if (lane == 31) warpsum[wid] = x;
    __syncthreads();
    if (wid == 0) {
        int w = warpsum[lane];
        int xw = w;
        #pragma unroll
        for (int o = 1; o < 32; o <<= 1) {
            int y = __shfl_up_sync(0xffffffffu, xw, o);
            if (lane >= o) xw += y;
        }
        warpsum[lane] = xw - w;   // exclusive warp prefix
    }
    __syncthreads();
    int run = (x - s) + warpsum[wid];   // global exclusive prefix of this chunk

    const int4 zero4 = make_int4(0, 0, 0, 0);
    #pragma unroll
    for (int j = 0; j < C; j += 4) {
        int idx = base + j;
        if (idx < NN) {
            int4 v = *(const int4*)&g_cnt[idx];
            int o0 = run;
            int o1 = o0 + v.x;
            int o2 = o1 + v.y;
            int o3 = o2 + v.z;
            run = o3 + v.w;
            int4 ov = make_int4(o0, o1, o2, o3);
            *(int4*)&g_off[idx] = ov;
            *(int4*)&g_cur[idx] = ov;
            *(int4*)&g_cnt[idx] = zero4;   // restore invariant for next replay
        }
    }
    if (tid == 0) g_off[NN] = NE;   // degree counts always sum to NE
}

// ---------------- fused logit + exp + scatter into CSR (2 edges/thread) ------
__global__ void k_scatter(const float* __restrict__ td, const int* __restrict__ src,
                          const int* __restrict__ dst, const float* __restrict__ omega) {
    int i = blockIdx.x * 256 + threadIdx.x;
    if (i * 2 >= NE) return;
    float2 t2 = ((const float2*)td)[i];
    int2   s2 = ((const int2*)src)[i];
    int2   d2 = ((const int2*)dst)[i];

    #pragma unroll
    for (int j = 0; j < 2; j++) {
        float t = (j == 0) ? t2.x : t2.y;
        int s   = (j == 0) ? s2.x : s2.y;
        int d   = (j == 0) ? d2.x : d2.y;
        float tt;
        if (t >= 0.f && t <= 1.f) {
            float u = t * (float)TABN;
            int i0 = (int)u;
            if (i0 >= TABN) i0 = TABN - 1;
            float f = u - (float)i0;
            float v0 = g_tab[i0], v1 = g_tab[i0 + 1];
            tt = v0 + f * (v1 - v0);
        } else {
            float acc = 0.f;
            for (int jj = 0; jj < THALF; jj++) {
                float sn, cs;
                sincosf(t * omega[jj], &sn, &cs);
                acc += sn * g_q[2 * jj] + cs * g_q[2 * jj + 1];
            }
            tt = acc * TSCALE;
        }
        float e = g_s1[s] + g_s2[d] + tt;
        e = (e > 0.f) ? e : 0.2f * e;       // LeakyReLU(0.2)
        float w = __expf(e);                // softmax numerator (logits are O(1))
        int pos = atomicAdd(&g_cur[d], 1);
        g_pair[pos] = make_float2(w, __int_as_float(s));
    }
}

// ---------------- warp-per-node single-pass softmax-aggregate ----------------
__global__ void k_agg(float* __restrict__ out) {
    int n = blockIdx.x * 8 + (threadIdx.x >> 5);
    int lane = threadIdx.x & 31;
    if (n >= NN) return;
    int start = g_off[n], end = g_off[n + 1];

    float wsum = 0.f, ax = 0.f, ay = 0.f;
    int k = start;
    for (; k + 4 <= end; k += 4) {
        float2 p0 = g_pair[k],     p1 = g_pair[k + 1];
        float2 p2 = g_pair[k + 2], p3 = g_pair[k + 3];
        int j0 = __float_as_int(p0.y), j1 = __float_as_int(p1.y);
        int j2 = __float_as_int(p2.y), j3 = __float_as_int(p3.y);
        __half2 h0 = ((const __half2*)(g_hv + (size_t)j0 * 64))[lane];
        __half2 h1 = ((const __half2*)(g_hv + (size_t)j1 * 64))[lane];
        __half2 h2 = ((const __half2*)(g_hv + (size_t)j2 * 64))[lane];
        __half2 h3 = ((const __half2*)(g_hv + (size_t)j3 * 64))[lane];
        float2 v0 = __half22float2(h0), v1 = __half22float2(h1);
        float2 v2 = __half22float2(h2), v3 = __half22float2(h3);
        wsum += (p0.x + p1.x) + (p2.x + p3.x);
        ax = fmaf(p0.x, v0.x, ax); ay = fmaf(p0.x, v0.y, ay);
        ax = fmaf(p1.x, v1.x, ax); ay = fmaf(p1.x, v1.y, ay);
        ax = fmaf(p2.x, v2.x, ax); ay = fmaf(p2.x, v2.y, ay);
        ax = fmaf(p3.x, v3.x, ax); ay = fmaf(p3.x, v3.y, ay);
    }
    for (; k < end; k++) {
        float2 p = g_pair[k];
        float2 v = __half22float2(
            ((const __half2*)(g_hv + (size_t)__float_as_int(p.y) * 64))[lane]);
        wsum += p.x;
        ax = fmaf(p.x, v.x, ax);
        ay = fmaf(p.x, v.y, ay);
    }
    float inv = (end > start) ? 1.f / wsum : 0.f;
    ((float2*)(out + (size_t)n * 64))[lane] = make_float2(ax * inv, ay * inv);
}

// ---------------- launcher: dual fork ----------------------------------------
extern "C" void kernel_launch(void* const* d_in, const int* in_sizes, int n_in,
                              void* d_out, int out_size) {
    const float* node_feats = (const float*)d_in[0];
    const float* time_diff  = (const float*)d_in[1];
    const int*   src        = (const int*)d_in[2];
    const int*   dst        = (const int*)d_in[3];
    const float* W          = (const float*)d_in[4];
    const float* Wv         = (const float*)d_in[5];
    const float* omega      = (const float*)d_in[6];
    const float* Wt         = (const float*)d_in[7];
    const float* a          = (const float*)d_in[8];
    float* out = (float*)d_out;

    static cudaStream_t sB = nullptr, sC = nullptr;
    static cudaEvent_t evFork = nullptr, evSetup = nullptr, evScan = nullptr, evHv = nullptr;
    if (!sB) {
        cudaStreamCreateWithFlags(&sB, cudaStreamNonBlocking);
        cudaStreamCreateWithFlags(&sC, cudaStreamNonBlocking);
        cudaEventCreateWithFlags(&evFork,  cudaEventDisableTiming);
        cudaEventCreateWithFlags(&evSetup, cudaEventDisableTiming);
        cudaEventCreateWithFlags(&evScan,  cudaEventDisableTiming);
        cudaEventCreateWithFlags(&evHv,    cudaEventDisableTiming);
    }

    // branch B: CSR build (depends only on dst; g_cnt is pre-zeroed invariant)
    cudaEventRecord(evFork, 0);
    cudaStreamWaitEvent(sB, evFork, 0);
    k_count  <<<(NE / 8 + 255) / 256, 256, 0, sB>>>(dst);
    k_scanall<<<1, 1024, 0, sB>>>();
    cudaEventRecord(evScan, sB);

    // main: weight prep
    k_setup<<<51, 256>>>(W, Wt, a, Wv, omega);
    cudaEventRecord(evSetup, 0);

    // branch C: value-projection GEMM (fma-pipe-bound; overlaps mem-bound work)
    cudaStreamWaitEvent(sC, evSetup, 0);
    k_hv<<<(NN + 63) / 64, 128, 0, sC>>>(node_feats);
    cudaEventRecord(evHv, sC);

    // main: per-node scalars -> scatter -> aggregate
    k_s12<<<(NN + 7) / 8, 256>>>(node_feats);
    cudaStreamWaitEvent(0, evScan, 0);
    k_scatter<<<(NE / 2 + 255) / 256, 256>>>(time_diff, src, dst, omega);
    cudaStreamWaitEvent(0, evHv, 0);
    k_agg<<<(NN + 7) / 8, 256>>>(out);
}

// round 9
// speedup vs baseline: 1.0769x; 1.0769x over previous
#include <cuda_runtime.h>
#include <cuda_fp16.h>
#include <math.h>

#define NN 50000
#define NE 800000
#define IND 128
#define OUTD 64
#define THALF 64
#define TABN 4096

// sqrt(1/128)
#define TSCALE 0.08838834764831845f

// ---------------- scratch (static __device__, no allocations) ----------------
__device__ float  g_p1[IND];
__device__ float  g_p2[IND];
__device__ float  g_q[2 * THALF];
__device__ float  g_tab[TABN + 1];
__device__ float  g_WvT[IND * OUTD];          // [k][c] layout
__device__ float  g_s1[NN];
__device__ float  g_s2[NN];
__device__ __half g_hv[NN * OUTD];            // fp16 value rows (halves gather BW)
__device__ float2 g_pair[NE];                 // (w=exp(leaky(e)), bitcast(src))
__device__ int    g_cnt[NN];                  // zero-init at load; self-restoring
__device__ int    g_off[NN + 1];
__device__ int    g_cur[NN];

// ---------------- packed f32x2 helpers ---------------------------------------
__device__ __forceinline__ unsigned long long fma2(unsigned long long a,
                                                   unsigned long long b,
                                                   unsigned long long c) {
    unsigned long long d;
    asm("fma.rn.f32x2 %0, %1, %2, %3;" : "=l"(d) : "l"(a), "l"(b), "l"(c));
    return d;
}
__device__ __forceinline__ unsigned long long splat2(float x) {
    unsigned long long d;
    asm("mov.b64 %0, {%1, %1};" : "=l"(d) : "f"(x));
    return d;
}
__device__ __forceinline__ float2 unpack2(unsigned long long v) {
    float lo, hi;
    asm("mov.b64 {%0, %1}, %2;" : "=f"(lo), "=f"(hi) : "l"(v));
    return make_float2(lo, hi);
}

// ---------------- fused setup kernel (weights-only prep) ---------------------
__global__ void k_setup(const float* __restrict__ W, const float* __restrict__ Wt,
                        const float* __restrict__ a, const float* __restrict__ Wv,
                        const float* __restrict__ omega) {
    int b = blockIdx.x;
    int t = threadIdx.x;

    if (b == 0) {
        if (t < 128) {
            float s = 0.f;
            #pragma unroll 8
            for (int i = 0; i < 64; i++) s += W[i * 128 + t] * a[i];
            g_p1[t] = s;
        } else {
            int k = t - 128;
            float s = 0.f;
            #pragma unroll 8
            for (int i = 0; i < 64; i++) s += W[i * 128 + k] * a[64 + i];
            g_p2[k] = s;
        }
    } else if (b == 1) {
        if (t < 128) {
            float s = 0.f;
            #pragma unroll 8
            for (int i = 0; i < 64; i++) s += Wt[i * 128 + t] * a[128 + i];
            g_q[t] = s;
        }
    } else if (b < 19) {
        __shared__ float qs[128];
        if (t < 128) {
            float s = 0.f;
            #pragma unroll 8
            for (int i = 0; i < 64; i++) s += Wt[i * 128 + t] * a[128 + i];
            qs[t] = s;
        }
        __syncthreads();
        int idx = (b - 2) * 256 + t;
        if (idx <= TABN) {
            float tt = (float)idx / (float)TABN;
            float s = 0.f;
            #pragma unroll 4
            for (int j = 0; j < THALF; j++) {
                float sn, cs;
                __sincosf(tt * omega[j], &sn, &cs);
                s += sn * qs[2 * j] + cs * qs[2 * j + 1];
            }
            g_tab[idx] = s * TSCALE;
        }
    } else {
        int j = (b - 19) * 256 + t;        // 0..8191
        int c = j & 63;
        int k = j >> 6;
        g_WvT[j] = Wv[c * 128 + k];
    }
}

// ---------------- per-node attention scalars s1/s2 (warp per node) -----------
__global__ void k_s12(const float* __restrict__ x) {
    int n = blockIdx.x * 8 + (threadIdx.x >> 5);
    int lane = threadIdx.x & 31;
    if (n >= NN) return;
    float4 v  = ((const float4*)(x + (size_t)n * IND))[lane];
    float4 p1 = ((const float4*)g_p1)[lane];
    float4 p2 = ((const float4*)g_p2)[lane];
    float d1 = v.x * p1.x + v.y * p1.y + v.z * p1.z + v.w * p1.w;
    float d2 = v.x * p2.x + v.y * p2.y + v.z * p2.z + v.w * p2.w;
    #pragma unroll
    for (int o = 16; o; o >>= 1) {
        d1 += __shfl_xor_sync(0xffffffffu, d1, o);
        d2 += __shfl_xor_sync(0xffffffffu, d2, o);
    }
    if (lane == 0) { g_s1[n] = d1; g_s2[n] = d2; }
}

// ---------------- hv = X @ Wv^T: 128x64 block tile, 8x8/thread, f32x2 --------
// B fragments come from g_WvT through L1 (32KB, resident); only X lives in smem
// (swizzled, 32KB). FFMA2:LDS ratio ~2:1 -> fma-pipe bound.
__global__ void __launch_bounds__(128) k_hv(const float* __restrict__ x) {
    __shared__ float sX[128 * 64];   // [row][k] with 2-bit XOR swizzle on col bits [4:5]

    int n0 = blockIdx.x * 128;
    int tid = threadIdx.x;
    int tr = (tid >> 3) * 8;         // row base (0..120)
    int tc = (tid & 7) * 8;          // col base (0..56)
    int sw = ((tid >> 3) & 3) << 4;  // per-thread column swizzle (rows tr..tr+7 share it)

    unsigned long long acc[8][4];
    #pragma unroll
    for (int r = 0; r < 8; r++)
        #pragma unroll
        for (int c = 0; c < 4; c++) acc[r][c] = 0ull;

    #pragma unroll
    for (int kt = 0; kt < 2; kt++) {
        // fill sX: 128 rows x 64 k, coalesced float4 reads, swizzled stores
        for (int i = tid; i < 2048; i += 128) {
            int r  = i >> 4;
            int c4 = i & 15;
            int n = n0 + r;
            float4 v = (n < NN)
                ? *(const float4*)(x + (size_t)n * 128 + kt * 64 + c4 * 4)
                : make_float4(0.f, 0.f, 0.f, 0.f);
            int col = (c4 * 4) ^ (((r >> 3) & 3) << 4);
            *(float4*)&sX[r * 64 + col] = v;
        }
        __syncthreads();

        const float* bbase = g_WvT + kt * 64 * 64 + tc;
        #pragma unroll 2
        for (int kk = 0; kk < 64; kk += 4) {
            float4 xr[8];
            int col = kk ^ sw;
            #pragma unroll
            for (int r = 0; r < 8; r++) xr[r] = *(float4*)&sX[(tr + r) * 64 + col];
            #pragma unroll
            for (int u = 0; u < 4; u++) {
                const float* brow = bbase + (kk + u) * 64;
                ulonglong2 bp0 = *(const ulonglong2*)(brow);
                ulonglong2 bp1 = *(const ulonglong2*)(brow + 4);
                #pragma unroll
                for (int r = 0; r < 8; r++) {
                    float xv = (u == 0) ? xr[r].x : (u == 1) ? xr[r].y
                             : (u == 2) ? xr[r].z : xr[r].w;
                    unsigned long long xs = splat2(xv);
                    acc[r][0] = fma2(xs, bp0.x, acc[r][0]);
                    acc[r][1] = fma2(xs, bp0.y, acc[r][1]);
                    acc[r][2] = fma2(xs, bp1.x, acc[r][2]);
                    acc[r][3] = fma2(xs, bp1.y, acc[r][3]);
                }
            }
        }
        __syncthreads();
    }

    #pragma unroll
    for (int r = 0; r < 8; r++) {
        int n = n0 + tr + r;
        if (n < NN) {
            __half2 h[4];
            #pragma unroll
            for (int c = 0; c < 4; c++) {
                float2 f = unpack2(acc[r][c]);
                h[c] = __floats2half2_rn(f.x, f.y);
            }
            *(uint4*)(g_hv + (size_t)n * 64 + tc) =
                make_uint4(*(unsigned*)&h[0], *(unsigned*)&h[1],
                           *(unsigned*)&h[2], *(unsigned*)&h[3]);
        }
    }
}

// ---------------- degree histogram (8 edges per thread, 2x int4 load) --------
__global__ void k_count(const int* __restrict__ dst) {
    int i = blockIdx.x * 256 + threadIdx.x;      // NE/8 = 100000 threads
    if (i * 8 >= NE) return;
    int4 a4 = ((const int4*)dst)[i * 2];
    int4 b4 = ((const int4*)dst)[i * 2 + 1];
    atomicAdd(&g_cnt[a4.x], 1);
    atomicAdd(&g_cnt[a4.y], 1);
    atomicAdd(&g_cnt[a4.z], 1);
    atomicAdd(&g_cnt[a4.w], 1);
    atomicAdd(&g_cnt[b4.x], 1);
    atomicAdd(&g_cnt[b4.y], 1);
    atomicAdd(&g_cnt[b4.z], 1);
    atomicAdd(&g_cnt[b4.w], 1);
}

// ---------------- single-kernel scan: g_cnt -> g_off/g_cur, self-zeroing -----
__global__ void __launch_bounds__(1024) k_scanall() {
    const int C = 52;   // 1024*52 = 53248 >= NN; NN%4==0 so int4 bounds are safe
    __shared__ int warpsum[32];
    int tid = threadIdx.x;
    int lane = tid & 31;
    int wid  = tid >> 5;
    int base = tid * C;

    int s = 0;
    #pragma unroll
    for (int j = 0; j < C; j += 4) {
        int idx = base + j;
        if (idx < NN) {
            int4 v = *(const int4*)&g_cnt[idx];
            s += (v.x + v.y) + (v.z + v.w);
        }
    }

    int x = s;
    #pragma unroll
    for (int o = 1; o < 32; o <<= 1) {
        int y = __shfl_up_sync(0xffffffffu, x, o);
        if (lane >= o) x += y;
    }
    if (lane == 31) warpsum[wid] = x;
    __syncthreads();
    if (wid == 0) {
        int w = warpsum[lane];
        int xw = w;
        #pragma unroll
        for (int o = 1; o < 32; o <<= 1) {
            int y = __shfl_up_sync(0xffffffffu, xw, o);
            if (lane >= o) xw += y;
        }
        warpsum[lane] = xw - w;
    }
    __syncthreads();
    int run = (x - s) + warpsum[wid];

    const int4 zero4 = make_int4(0, 0, 0, 0);
    #pragma unroll
    for (int j = 0; j < C; j += 4) {
        int idx = base + j;
        if (idx < NN) {
            int4 v = *(const int4*)&g_cnt[idx];
            int o0 = run;
            int o1 = o0 + v.x;
            int o2 = o1 + v.y;
            int o3 = o2 + v.z;
            run = o3 + v.w;
            int4 ov = make_int4(o0, o1, o2, o3);
            *(int4*)&g_off[idx] = ov;
            *(int4*)&g_cur[idx] = ov;
            *(int4*)&g_cnt[idx] = zero4;   // restore invariant for next replay
        }
    }
    if (tid == 0) g_off[NN] = NE;
}

// ---------------- fused logit + exp + scatter into CSR (2 edges/thread) ------
__global__ void k_scatter(const float* __restrict__ td, const int* __restrict__ src,
                          const int* __restrict__ dst, const float* __restrict__ omega) {
    int i = blockIdx.x * 256 + threadIdx.x;
    if (i * 2 >= NE) return;
    float2 t2 = ((const float2*)td)[i];
    int2   s2 = ((const int2*)src)[i];
    int2   d2 = ((const int2*)dst)[i];

    #pragma unroll
    for (int j = 0; j < 2; j++) {
        float t = (j == 0) ? t2.x : t2.y;
        int s   = (j == 0) ? s2.x : s2.y;
        int d   = (j == 0) ? d2.x : d2.y;
        float tt;
        if (t >= 0.f && t <= 1.f) {
            float u = t * (float)TABN;
            int i0 = (int)u;
            if (i0 >= TABN) i0 = TABN - 1;
            float f = u - (float)i0;
            float v0 = g_tab[i0], v1 = g_tab[i0 + 1];
            tt = v0 + f * (v1 - v0);
        } else {
            float acc = 0.f;
            for (int jj = 0; jj < THALF; jj++) {
                float sn, cs;
                sincosf(t * omega[jj], &sn, &cs);
                acc += sn * g_q[2 * jj] + cs * g_q[2 * jj + 1];
            }
            tt = acc * TSCALE;
        }
        float e = g_s1[s] + g_s2[d] + tt;
        e = (e > 0.f) ? e : 0.2f * e;       // LeakyReLU(0.2)
        float w = __expf(e);                // softmax numerator (logits are O(1))
        int pos = atomicAdd(&g_cur[d], 1);
        g_pair[pos] = make_float2(w, __int_as_float(s));
    }
}

// ---------------- warp-per-node single-pass softmax-aggregate ----------------
__global__ void k_agg(float* __restrict__ out) {
    int n = blockIdx.x * 8 + (threadIdx.x >> 5);
    int lane = threadIdx.x & 31;
    if (n >= NN) return;
    int start = g_off[n], end = g_off[n + 1];

    float wsum = 0.f, ax = 0.f, ay = 0.f;
    int k = start;
    for (; k + 4 <= end; k += 4) {
        float2 p0 = g_pair[k],     p1 = g_pair[k + 1];
        float2 p2 = g_pair[k + 2], p3 = g_pair[k + 3];
        int j0 = __float_as_int(p0.y), j1 = __float_as_int(p1.y);
        int j2 = __float_as_int(p2.y), j3 = __float_as_int(p3.y);
        __half2 h0 = ((const __half2*)(g_hv + (size_t)j0 * 64))[lane];
        __half2 h1 = ((const __half2*)(g_hv + (size_t)j1 * 64))[lane];
        __half2 h2 = ((const __half2*)(g_hv + (size_t)j2 * 64))[lane];
        __half2 h3 = ((const __half2*)(g_hv + (size_t)j3 * 64))[lane];
        float2 v0 = __half22float2(h0), v1 = __half22float2(h1);
        float2 v2 = __half22float2(h2), v3 = __half22float2(h3);
        wsum += (p0.x + p1.x) + (p2.x + p3.x);
        ax = fmaf(p0.x, v0.x, ax); ay = fmaf(p0.x, v0.y, ay);
        ax = fmaf(p1.x, v1.x, ax); ay = fmaf(p1.x, v1.y, ay);
        ax = fmaf(p2.x, v2.x, ax); ay = fmaf(p2.x, v2.y, ay);
        ax = fmaf(p3.x, v3.x, ax); ay = fmaf(p3.x, v3.y, ay);
    }
    for (; k < end; k++) {
        float2 p = g_pair[k];
        float2 v = __half22float2(
            ((const __half2*)(g_hv + (size_t)__float_as_int(p.y) * 64))[lane]);
        wsum += p.x;
        ax = fmaf(p.x, v.x, ax);
        ay = fmaf(p.x, v.y, ay);
    }
    float inv = (end > start) ? 1.f / wsum : 0.f;
    ((float2*)(out + (size_t)n * 64))[lane] = make_float2(ax * inv, ay * inv);
}

// ---------------- launcher: dual fork ----------------------------------------
extern "C" void kernel_launch(void* const* d_in, const int* in_sizes, int n_in,
                              void* d_out, int out_size) {
    const float* node_feats = (const float*)d_in[0];
    const float* time_diff  = (const float*)d_in[1];
    const int*   src        = (const int*)d_in[2];
    const int*   dst        = (const int*)d_in[3];
    const float* W          = (const float*)d_in[4];
    const float* Wv         = (const float*)d_in[5];
    const float* omega      = (const float*)d_in[6];
    const float* Wt         = (const float*)d_in[7];
    const float* a          = (const float*)d_in[8];
    float* out = (float*)d_out;

    static cudaStream_t sB = nullptr, sC = nullptr;
    static cudaEvent_t evFork = nullptr, evSetup = nullptr, evScan = nullptr, evHv = nullptr;
    if (!sB) {
        cudaStreamCreateWithFlags(&sB, cudaStreamNonBlocking);
        cudaStreamCreateWithFlags(&sC, cudaStreamNonBlocking);
        cudaEventCreateWithFlags(&evFork,  cudaEventDisableTiming);
        cudaEventCreateWithFlags(&evSetup, cudaEventDisableTiming);
        cudaEventCreateWithFlags(&evScan,  cudaEventDisableTiming);
        cudaEventCreateWithFlags(&evHv,    cudaEventDisableTiming);
    }

    // branch B: CSR build (depends only on dst; g_cnt is pre-zeroed invariant)
    cudaEventRecord(evFork, 0);
    cudaStreamWaitEvent(sB, evFork, 0);
    k_count  <<<(NE / 8 + 255) / 256, 256, 0, sB>>>(dst);
    k_scanall<<<1, 1024, 0, sB>>>();
    cudaEventRecord(evScan, sB);

    // main: weight prep
    k_setup<<<51, 256>>>(W, Wt, a, Wv, omega);
    cudaEventRecord(evSetup, 0);

    // branch C: value-projection GEMM (fma-pipe-bound; overlaps mem-bound work)
    cudaStreamWaitEvent(sC, evSetup, 0);
    k_hv<<<(NN + 127) / 128, 128, 0, sC>>>(node_feats);
    cudaEventRecord(evHv, sC);

    // main: per-node scalars -> scatter -> aggregate
    k_s12<<<(NN + 7) / 8, 256>>>(node_feats);
    cudaStreamWaitEvent(0, evScan, 0);
    k_scatter<<<(NE / 2 + 255) / 256, 256>>>(time_diff, src, dst, omega);
    cudaStreamWaitEvent(0, evHv, 0);
    k_agg<<<(NN + 7) / 8, 256>>>(out);
}